// round 7
// baseline (speedup 1.0000x reference)
#include <cuda_runtime.h>
#include <math.h>

#define FM_C 256
#define FM_H 200
#define FM_W 200
#define IIH 201
#define IIW 201
#define NBOX 1024
#define OH 7
#define OW 7
#define NBINS 49

// Integral image scratch, channel-last layout: [y][x][c], y,x in 0..200.
// After k1: ii[y+1][x+1][c] = x-cumsum of fm row y. After k2: full 2D cumsum.
__device__ float g_ii[IIH * IIW * FM_C];      // 41.4 MB

// ---------------------------------------------------------------------------
// K1': x-cumsum fused with transpose [C][H][W] -> [y+1][x+1][C].
// Grid (8 c-tiles, 200 y-rows) = 1600 independent blocks of 1024 threads.
// Warp w scans channel c0+w's row y via shfl-prefix chunks of 32; shared
// transpose (double-buffered, 1 barrier/chunk) makes global stores 128B
// coalesced along c. No cross-block dependencies, no fixups.
// ---------------------------------------------------------------------------
#define K1_NCHUNK 7   // ceil(200/32)

__global__ void __launch_bounds__(1024) k1_xcum_transpose(const float* __restrict__ fm) {
    __shared__ float sh[2][32][33];
    const int w = threadIdx.x >> 5;        // warp = channel offset 0..31
    const int l = threadIdx.x & 31;        // lane = x offset within chunk
    const int c0 = blockIdx.x * 32;
    const int y  = blockIdx.y;             // fm row 0..199

    // --- zero pads ---
    // x=0 column of this block's output row: ii[y+1][0][c0..c0+31]
    if (w == 0) {
        g_ii[((size_t)(y + 1) * IIW) * FM_C + c0 + l] = 0.0f;
    }
    // y=0 plane handled by y==0 blocks: ii[0][x][c0..c0+31] for all x
    if (y == 0) {
        for (int idx = threadIdx.x; idx < IIW * 32; idx += 1024) {
            const int x = idx >> 5;
            const int c = idx & 31;
            g_ii[(size_t)x * FM_C + c0 + c] = 0.0f;
        }
    }

    const float* src = fm + (size_t)(c0 + w) * (FM_H * FM_W) + (size_t)y * FM_W;
    float* dstrow = g_ii + ((size_t)(y + 1) * IIW) * FM_C;

    float carry = 0.0f;
    #pragma unroll
    for (int ch = 0; ch < K1_NCHUNK; ch++) {
        const int x = ch * 32 + l;
        float v = (x < FM_W) ? __ldcs(&src[x]) : 0.0f;
        // inclusive warp scan
        #pragma unroll
        for (int d = 1; d < 32; d <<= 1) {
            float t = __shfl_up_sync(0xFFFFFFFFu, v, d);
            if (l >= d) v += t;
        }
        v += carry;
        carry = __shfl_sync(0xFFFFFFFFu, v, 31);

        const int buf = ch & 1;
        sh[buf][w][l] = v;
        __syncthreads();
        // warp w stores x-column ch*32+w, channels c0..c0+31 (lane = c)
        const int xg = ch * 32 + w;
        if (xg < FM_W) {
            dstrow[(size_t)(xg + 1) * FM_C + c0 + l] = sh[buf][l][w];
        }
        // double buffer: next chunk writes the other buffer; this one is only
        // rewritten after the next barrier, which follows all its reads.
    }
}

// ---------------------------------------------------------------------------
// K2': y-cumsum in-place, channel-last. One block per x-column (200 blocks,
// x=1..200), thread per channel. Double-buffered 20-wide batches: load batch
// i+1 while accumulating batch i. No fixups (x-scan already done by k1).
// ---------------------------------------------------------------------------
#define K2B 20
#define K2NB (FM_H / K2B)    // 10
__global__ void __launch_bounds__(256) k2_ycum() {
    const int x = blockIdx.x + 1;          // 1..200
    const int c = threadIdx.x;             // 0..255
    float* col = g_ii + (size_t)x * FM_C + c;   // element y at offset y*IIW*FM_C
    const size_t ystride = (size_t)IIW * FM_C;

    float va[K2B], vb[K2B];
    #pragma unroll
    for (int j = 0; j < K2B; j++) va[j] = col[(size_t)(1 + j) * ystride];

    float acc = 0.0f;
    #pragma unroll 1
    for (int i = 0; i < K2NB; i++) {
        if (i + 1 < K2NB) {
            const int yb = 1 + (i + 1) * K2B;
            #pragma unroll
            for (int j = 0; j < K2B; j++) vb[j] = col[(size_t)(yb + j) * ystride];
        }
        const int y0_ = 1 + i * K2B;
        #pragma unroll
        for (int j = 0; j < K2B; j++) {
            acc += va[j];
            col[(size_t)(y0_ + j) * ystride] = acc;
        }
        #pragma unroll
        for (int j = 0; j < K2B; j++) va[j] = vb[j];
    }
}

// ---------------------------------------------------------------------------
// K3: gather. One block per TWO boxes (512 blocks, single wave).
// warp lanes = 8 channel-groups x 4 bins; S_PAD=25 conflict-free staging.
// Output stores evict-first (.cs) so streaming writes don't evict ii from L2.
// ---------------------------------------------------------------------------
#define S_PAD 25
#define BPB 2   // boxes per block

template <int NB, int BIN0>
__device__ __forceinline__ void gather_pass(const float4* __restrict__ ii4,
                                            const int* __restrict__ soff,
                                            const float* __restrict__ srarea,
                                            float* __restrict__ sh,
                                            float* __restrict__ outn,
                                            int tid) {
    const int warp = tid >> 5;
    const int lane = tid & 31;
    const int cg = warp * 8 + (lane & 7);   // 0..63 channel group (float4)
    const int bsl = lane >> 3;              // 0..3 bin slot

    #pragma unroll
    for (int bb = bsl; bb < NB; bb += 4) {
        const int b = BIN0 + bb;
        const int o0 = soff[b * 4 + 0];
        const int o1 = soff[b * 4 + 1];
        const int o2 = soff[b * 4 + 2];
        const int o3 = soff[b * 4 + 3];
        const float4 A = ii4[o0 + cg];
        const float4 B = ii4[o1 + cg];
        const float4 C = ii4[o2 + cg];
        const float4 D = ii4[o3 + cg];
        const float ra = srarea[b];
        const int cb = cg * 4;
        sh[(cb + 0) * S_PAD + bb] = (A.x - B.x - C.x + D.x) * ra;
        sh[(cb + 1) * S_PAD + bb] = (A.y - B.y - C.y + D.y) * ra;
        sh[(cb + 2) * S_PAD + bb] = (A.z - B.z - C.z + D.z) * ra;
        sh[(cb + 3) * S_PAD + bb] = (A.w - B.w - C.w + D.w) * ra;
    }
    __syncthreads();
    #pragma unroll 4
    for (int idx = tid; idx < FM_C * NB; idx += 256) {
        const int c = idx / NB;               // NB constexpr -> magic multiply
        const int b = idx - c * NB;
        __stcs(&outn[c * NBINS + BIN0 + b], sh[c * S_PAD + b]);
    }
    __syncthreads();
}

__global__ void __launch_bounds__(256) k3_gather(const float* __restrict__ boxes,
                                                 float* __restrict__ out) {
    __shared__ float sh[FM_C * S_PAD];       // 25.6 KB
    __shared__ int   soff[BPB][NBINS * 4];
    __shared__ float srarea[BPB][NBINS];
    const int tid = threadIdx.x;

    if (tid < BPB * NBINS) {
        const int bx = tid / NBINS;
        const int bin = tid - bx * NBINS;
        const int n = blockIdx.x * BPB + bx;

        const float bx1 = __ldg(&boxes[n * 4 + 0]);
        const float by1 = __ldg(&boxes[n * 4 + 1]);
        const float bx2 = __ldg(&boxes[n * 4 + 2]);
        const float by2 = __ldg(&boxes[n * 4 + 3]);

        // scale = 200/800 = 0.25 exactly (bit-exact with reference)
        const int b0 = (int)floorf(bx1 * 0.25f);
        const int b1 = (int)floorf(by1 * 0.25f);
        const int b2 = (int)floorf(bx2 * 0.25f);
        const int b3 = (int)floorf(by2 * 0.25f);

        const int x1 = min(max(b0, 0), FM_W - 1);
        const int y1 = min(max(b1, 0), FM_H - 1);
        const int x2 = min(max(b2 + 1, x1 + 1), FM_W);
        const int y2 = min(max(b3 + 1, y1 + 1), FM_H);
        const int rh = y2 - y1;
        const int rw = x2 - x1;

        const int i = bin / OW;
        const int j = bin - i * OW;
        const int rs_ = y1 + (i * rh) / OH;
        const int re_ = y1 + ((i + 1) * rh + OH - 1) / OH;
        const int cs_ = x1 + (j * rw) / OW;
        const int ce_ = x1 + ((j + 1) * rw + OW - 1) / OW;

        soff[bx][bin * 4 + 0] = (re_ * IIW + ce_) * (FM_C / 4);
        soff[bx][bin * 4 + 1] = (rs_ * IIW + ce_) * (FM_C / 4);
        soff[bx][bin * 4 + 2] = (re_ * IIW + cs_) * (FM_C / 4);
        soff[bx][bin * 4 + 3] = (rs_ * IIW + cs_) * (FM_C / 4);
        srarea[bx][bin] = 1.0f / (float)((re_ - rs_) * (ce_ - cs_));
    }
    __syncthreads();

    const float4* ii4 = (const float4*)g_ii;

    #pragma unroll
    for (int bx = 0; bx < BPB; bx++) {
        const int n = blockIdx.x * BPB + bx;
        float* outn = out + (size_t)n * (FM_C * NBINS);
        gather_pass<25, 0>(ii4, soff[bx], srarea[bx], sh, outn, tid);
        gather_pass<24, 25>(ii4, soff[bx], srarea[bx], sh, outn, tid);
    }
}

// ---------------------------------------------------------------------------
extern "C" void kernel_launch(void* const* d_in, const int* in_sizes, int n_in,
                              void* d_out, int out_size) {
    const float* fm    = (const float*)d_in[0];   // [1,256,200,200] fp32
    const float* boxes = (const float*)d_in[1];   // [1024,4] fp32
    float* out = (float*)d_out;                   // [1024,256,7,7] fp32

    {
        dim3 grid(FM_C / 32, FM_H);                  // (8, 200) = 1600 blocks
        k1_xcum_transpose<<<grid, 1024>>>(fm);
    }
    k2_ycum<<<FM_H, 256>>>();
    k3_gather<<<NBOX / BPB, 256>>>(boxes, out);
}

// round 8
// speedup vs baseline: 1.3877x; 1.3877x over previous
#include <cuda_runtime.h>
#include <math.h>

#define FM_C 256
#define FM_H 200
#define FM_W 200
#define IIH 201
#define IIW 201
#define NBOX 1024
#define OH 7
#define OW 7
#define NBINS 49

// Integral image scratch, channel-last layout: [y][x][c], y,x in 0..200.
// After k1: ii[y+1][x+1][c] = x-cumsum of fm row y. After k2: full 2D cumsum.
__device__ float g_ii[IIH * IIW * FM_C];      // 41.4 MB

// ---------------------------------------------------------------------------
// K1: x-cumsum fused with transpose [C][H][W] -> [y+1][x+1][C].
// Grid (8 c-tiles, 200 y-rows), 1024 threads (32 warps). Warp w owns channel
// c0+w's row y. All 7 x-chunks loaded upfront (MLP=7); the 7 warp-scans run
// with full ILP (carry applied as a 7-FADD chain afterwards); ONE barrier,
// then transposed 128B-coalesced stores.
// ---------------------------------------------------------------------------
#define K1C 7   // ceil(200/32)

__global__ void __launch_bounds__(1024) k1_xcum_transpose(const float* __restrict__ fm) {
    __shared__ float sh[K1C][32][33];      // 29.5 KB
    const int w = threadIdx.x >> 5;        // warp = channel offset 0..31
    const int l = threadIdx.x & 31;        // lane = x offset within chunk
    const int c0 = blockIdx.x * 32;
    const int y  = blockIdx.y;             // fm row 0..199

    // --- zero pads ---
    if (w == 0) {   // x=0 column of this output row: ii[y+1][0][c]
        g_ii[((size_t)(y + 1) * IIW) * FM_C + c0 + l] = 0.0f;
    }
    if (y == 0) {   // y=0 plane: ii[0][x][c] for all x
        for (int idx = threadIdx.x; idx < IIW * 32; idx += 1024) {
            const int x = idx >> 5;
            const int c = idx & 31;
            g_ii[(size_t)x * FM_C + c0 + c] = 0.0f;
        }
    }

    const float* src = fm + (size_t)(c0 + w) * (FM_H * FM_W) + (size_t)y * FM_W;
    float* dstrow = g_ii + ((size_t)(y + 1) * IIW) * FM_C;

    // 1) load all chunks (independent -> MLP=7)
    float v[K1C];
    #pragma unroll
    for (int ch = 0; ch < K1C; ch++) {
        const int x = ch * 32 + l;
        v[ch] = (x < FM_W) ? __ldcs(&src[x]) : 0.0f;
    }

    // 2) scan all chunks independently (ILP across the 7 shfl trees)
    #pragma unroll
    for (int d = 1; d < 32; d <<= 1) {
        #pragma unroll
        for (int ch = 0; ch < K1C; ch++) {
            float t = __shfl_up_sync(0xFFFFFFFFu, v[ch], d);
            if (l >= d) v[ch] += t;
        }
    }

    // 3) chain chunk sums (serial part = 6 FADDs)
    float off = 0.0f;
    #pragma unroll
    for (int ch = 0; ch < K1C; ch++) {
        const float s = __shfl_sync(0xFFFFFFFFu, v[ch], 31);
        v[ch] += off;
        off += s;
    }

    // 4) stage transpose; one barrier; coalesced stores (lane = channel)
    #pragma unroll
    for (int ch = 0; ch < K1C; ch++) {
        sh[ch][w][l] = v[ch];
    }
    __syncthreads();
    #pragma unroll
    for (int ch = 0; ch < K1C; ch++) {
        const int xg = ch * 32 + w;        // warp w writes x-column xg of chunk ch
        if (xg < FM_W) {
            dstrow[(size_t)(xg + 1) * FM_C + c0 + l] = sh[ch][l][w];
        }
    }
}

// ---------------------------------------------------------------------------
// K2: y-cumsum in-place, channel-last. 400 blocks (200 x-columns x 2
// c-halves), 128 threads. Double-buffered 20-wide batches: load batch i+1
// while accumulating batch i. No fixups.
// ---------------------------------------------------------------------------
#define K2B 20
#define K2NB (FM_H / K2B)    // 10
__global__ void __launch_bounds__(128) k2_ycum() {
    const int x = blockIdx.x + 1;                    // 1..200
    const int c = blockIdx.y * 128 + threadIdx.x;    // 0..255
    float* col = g_ii + (size_t)x * FM_C + c;
    const size_t ystride = (size_t)IIW * FM_C;

    float va[K2B], vb[K2B];
    #pragma unroll
    for (int j = 0; j < K2B; j++) va[j] = col[(size_t)(1 + j) * ystride];

    float acc = 0.0f;
    #pragma unroll 1
    for (int i = 0; i < K2NB; i++) {
        if (i + 1 < K2NB) {
            const int yb = 1 + (i + 1) * K2B;
            #pragma unroll
            for (int j = 0; j < K2B; j++) vb[j] = col[(size_t)(yb + j) * ystride];
        }
        const int y0_ = 1 + i * K2B;
        #pragma unroll
        for (int j = 0; j < K2B; j++) {
            acc += va[j];
            col[(size_t)(y0_ + j) * ystride] = acc;
        }
        #pragma unroll
        for (int j = 0; j < K2B; j++) va[j] = vb[j];
    }
}

// ---------------------------------------------------------------------------
// K3: gather. One block per TWO boxes (512 blocks, single wave).
// warp lanes = 8 channel-groups x 4 bins; S_PAD=25 conflict-free staging.
// Output stores evict-first (.cs) so streaming writes don't evict ii from L2.
// ---------------------------------------------------------------------------
#define S_PAD 25
#define BPB 2   // boxes per block

template <int NB, int BIN0>
__device__ __forceinline__ void gather_pass(const float4* __restrict__ ii4,
                                            const int* __restrict__ soff,
                                            const float* __restrict__ srarea,
                                            float* __restrict__ sh,
                                            float* __restrict__ outn,
                                            int tid) {
    const int warp = tid >> 5;
    const int lane = tid & 31;
    const int cg = warp * 8 + (lane & 7);   // 0..63 channel group (float4)
    const int bsl = lane >> 3;              // 0..3 bin slot

    #pragma unroll
    for (int bb = bsl; bb < NB; bb += 4) {
        const int b = BIN0 + bb;
        const int o0 = soff[b * 4 + 0];
        const int o1 = soff[b * 4 + 1];
        const int o2 = soff[b * 4 + 2];
        const int o3 = soff[b * 4 + 3];
        const float4 A = ii4[o0 + cg];
        const float4 B = ii4[o1 + cg];
        const float4 C = ii4[o2 + cg];
        const float4 D = ii4[o3 + cg];
        const float ra = srarea[b];
        const int cb = cg * 4;
        sh[(cb + 0) * S_PAD + bb] = (A.x - B.x - C.x + D.x) * ra;
        sh[(cb + 1) * S_PAD + bb] = (A.y - B.y - C.y + D.y) * ra;
        sh[(cb + 2) * S_PAD + bb] = (A.z - B.z - C.z + D.z) * ra;
        sh[(cb + 3) * S_PAD + bb] = (A.w - B.w - C.w + D.w) * ra;
    }
    __syncthreads();
    #pragma unroll 4
    for (int idx = tid; idx < FM_C * NB; idx += 256) {
        const int c = idx / NB;               // NB constexpr -> magic multiply
        const int b = idx - c * NB;
        __stcs(&outn[c * NBINS + BIN0 + b], sh[c * S_PAD + b]);
    }
    __syncthreads();
}

__global__ void __launch_bounds__(256) k3_gather(const float* __restrict__ boxes,
                                                 float* __restrict__ out) {
    __shared__ float sh[FM_C * S_PAD];       // 25.6 KB
    __shared__ int   soff[BPB][NBINS * 4];
    __shared__ float srarea[BPB][NBINS];
    const int tid = threadIdx.x;

    if (tid < BPB * NBINS) {
        const int bx = tid / NBINS;
        const int bin = tid - bx * NBINS;
        const int n = blockIdx.x * BPB + bx;

        const float bx1 = __ldg(&boxes[n * 4 + 0]);
        const float by1 = __ldg(&boxes[n * 4 + 1]);
        const float bx2 = __ldg(&boxes[n * 4 + 2]);
        const float by2 = __ldg(&boxes[n * 4 + 3]);

        // scale = 200/800 = 0.25 exactly (bit-exact with reference)
        const int b0 = (int)floorf(bx1 * 0.25f);
        const int b1 = (int)floorf(by1 * 0.25f);
        const int b2 = (int)floorf(bx2 * 0.25f);
        const int b3 = (int)floorf(by2 * 0.25f);

        const int x1 = min(max(b0, 0), FM_W - 1);
        const int y1 = min(max(b1, 0), FM_H - 1);
        const int x2 = min(max(b2 + 1, x1 + 1), FM_W);
        const int y2 = min(max(b3 + 1, y1 + 1), FM_H);
        const int rh = y2 - y1;
        const int rw = x2 - x1;

        const int i = bin / OW;
        const int j = bin - i * OW;
        const int rs_ = y1 + (i * rh) / OH;
        const int re_ = y1 + ((i + 1) * rh + OH - 1) / OH;
        const int cs_ = x1 + (j * rw) / OW;
        const int ce_ = x1 + ((j + 1) * rw + OW - 1) / OW;

        soff[bx][bin * 4 + 0] = (re_ * IIW + ce_) * (FM_C / 4);
        soff[bx][bin * 4 + 1] = (rs_ * IIW + ce_) * (FM_C / 4);
        soff[bx][bin * 4 + 2] = (re_ * IIW + cs_) * (FM_C / 4);
        soff[bx][bin * 4 + 3] = (rs_ * IIW + cs_) * (FM_C / 4);
        srarea[bx][bin] = 1.0f / (float)((re_ - rs_) * (ce_ - cs_));
    }
    __syncthreads();

    const float4* ii4 = (const float4*)g_ii;

    #pragma unroll
    for (int bx = 0; bx < BPB; bx++) {
        const int n = blockIdx.x * BPB + bx;
        float* outn = out + (size_t)n * (FM_C * NBINS);
        gather_pass<25, 0>(ii4, soff[bx], srarea[bx], sh, outn, tid);
        gather_pass<24, 25>(ii4, soff[bx], srarea[bx], sh, outn, tid);
    }
}

// ---------------------------------------------------------------------------
extern "C" void kernel_launch(void* const* d_in, const int* in_sizes, int n_in,
                              void* d_out, int out_size) {
    const float* fm    = (const float*)d_in[0];   // [1,256,200,200] fp32
    const float* boxes = (const float*)d_in[1];   // [1024,4] fp32
    float* out = (float*)d_out;                   // [1024,256,7,7] fp32

    {
        dim3 grid(FM_C / 32, FM_H);                  // (8, 200) = 1600 blocks
        k1_xcum_transpose<<<grid, 1024>>>(fm);
    }
    {
        dim3 grid(FM_H, 2);                          // 400 blocks
        k2_ycum<<<grid, 128>>>();
    }
    k3_gather<<<NBOX / BPB, 256>>>(boxes, out);
}